// round 1
// baseline (speedup 1.0000x reference)
#include <cuda_runtime.h>
#include <math.h>

#define HH 112
#define CC 32
#define W2 49
#define TOPK 4
#define KC 196      // TOPK * W2
#define NW 256
#define HEADS 8
#define SCALEF 0.17677669529663687f   // 32^-0.5

#define KPAD 36     // K row pad (bank-conflict-free column reads)
#define SPAD 200    // S row pad (float4-aligned)

__global__ __launch_bounds__(256)
void wsa_kernel(const float* __restrict__ q, const float* __restrict__ k,
                const float* __restrict__ v, const int* __restrict__ indices,
                float* __restrict__ out)
{
    extern __shared__ float sm[];
    float* Qs = sm;                    // 49*32   = 1568 floats
    float* Ks = Qs + W2*CC;            // 196*36  = 7056
    float* Vs = Ks + KC*KPAD;          // 196*32  = 6272
    float* S  = Vs + KC*CC;            // 49*200  = 9800

    __shared__ int sIdx[TOPK];

    const int w = blockIdx.x;
    const int h = blockIdx.y;
    const int b = blockIdx.z;
    const int t = threadIdx.x;
    const int wy = w >> 4, wx = w & 15;

    const size_t base = ((size_t)(b*HEADS + h)) * (size_t)(HH*HH*CC);
    const float* qb = q + base;
    const float* kb = k + base;
    const float* vb = v + base;

    if (t < TOPK)
        sIdx[t] = indices[(((size_t)(b*HEADS + h))*NW + w)*TOPK + t];

    // ---- load Q window: 49 rows x 32 ch (float4) ----
    for (int i = t; i < W2*8; i += 256) {
        int p = i >> 3, c4 = (i & 7) << 2;
        int y = wy*7 + p/7, x = wx*7 + p%7;
        *(float4*)(Qs + p*CC + c4) =
            *(const float4*)(qb + ((size_t)(y*HH + x))*CC + c4);
    }
    __syncthreads();

    // ---- gather K,V: topk windows x 49 rows x 32 ch ----
    for (int i = t; i < KC*8; i += 256) {
        int row = i >> 3, c4 = (i & 7) << 2;
        int tt = row / W2, p = row % W2;
        int ws = sIdx[tt];
        int y = (ws >> 4)*7 + p/7, x = (ws & 15)*7 + p%7;
        size_t off = ((size_t)(y*HH + x))*CC + c4;
        *(float4*)(Ks + row*KPAD + c4) = *(const float4*)(kb + off);
        *(float4*)(Vs + row*CC   + c4) = *(const float4*)(vb + off);
    }
    __syncthreads();

    // ---- phase 2: S[p][j] = scale * <Q[p], K[j]>  (thread j owns a column) ----
    if (t < KC) {
        float acc[W2];
        #pragma unroll
        for (int p = 0; p < W2; p++) acc[p] = 0.f;
        #pragma unroll 1
        for (int c4 = 0; c4 < 8; c4++) {
            float4 kk = *(float4*)(Ks + t*KPAD + (c4 << 2));
            #pragma unroll
            for (int p = 0; p < W2; p++) {
                float4 qq = *(float4*)(Qs + p*CC + (c4 << 2));   // warp broadcast
                acc[p] = fmaf(qq.x, kk.x, fmaf(qq.y, kk.y,
                         fmaf(qq.z, kk.z, fmaf(qq.w, kk.w, acc[p]))));
            }
        }
        #pragma unroll
        for (int p = 0; p < W2; p++) S[p*SPAD + t] = acc[p] * SCALEF;
    }
    __syncthreads();

    // ---- phase 3: row softmax (one warp per row, rows strided by 8) ----
    {
        int warp = t >> 5, lane = t & 31;
        for (int p = warp; p < W2; p += 8) {
            float vals[7];
            float m = -INFINITY;
            #pragma unroll
            for (int it = 0; it < 7; it++) {
                int j = lane + (it << 5);
                float x = (j < KC) ? S[p*SPAD + j] : -INFINITY;
                vals[it] = x;
                m = fmaxf(m, x);
            }
            #pragma unroll
            for (int o = 16; o > 0; o >>= 1)
                m = fmaxf(m, __shfl_xor_sync(0xffffffffu, m, o));
            float s = 0.f;
            #pragma unroll
            for (int it = 0; it < 7; it++) {
                float e = __expf(vals[it] - m);   // masked lanes: exp(-inf)=0
                vals[it] = e; s += e;
            }
            #pragma unroll
            for (int o = 16; o > 0; o >>= 1)
                s += __shfl_xor_sync(0xffffffffu, s, o);
            float inv = 1.0f / s;
            #pragma unroll
            for (int it = 0; it < 7; it++) {
                int j = lane + (it << 5);
                if (j < KC) S[p*SPAD + j] = vals[it] * inv;
            }
        }
    }
    __syncthreads();

    // ---- phase 4: O = P @ V ; thread (pg,c) owns rows p = pg + 8k, channel c ----
    {
        int c = t & 31, pg = t >> 5;
        float o[7];
        #pragma unroll
        for (int kk2 = 0; kk2 < 7; kk2++) o[kk2] = 0.f;
        #pragma unroll 1
        for (int j4 = 0; j4 < 49; j4++) {
            int j = j4 << 2;
            float v0 = Vs[(j+0)*CC + c];
            float v1 = Vs[(j+1)*CC + c];
            float v2 = Vs[(j+2)*CC + c];
            float v3 = Vs[(j+3)*CC + c];
            #pragma unroll
            for (int kk2 = 0; kk2 < 7; kk2++) {
                int p = pg + (kk2 << 3);
                if (p < W2) {
                    float4 pp = *(float4*)(S + p*SPAD + j);      // warp broadcast
                    o[kk2] = fmaf(pp.x, v0, fmaf(pp.y, v1,
                             fmaf(pp.z, v2, fmaf(pp.w, v3, o[kk2]))));
                }
            }
        }
        // ---- write out: out[b, y, x, h*32 + c] ----
        float* ob = out + ((size_t)b*(HH*HH))*256 + h*CC + c;
        #pragma unroll
        for (int kk2 = 0; kk2 < 7; kk2++) {
            int p = pg + (kk2 << 3);
            if (p < W2) {
                int y = wy*7 + p/7, x = wx*7 + p%7;
                ob[(size_t)(y*HH + x)*256] = o[kk2];
            }
        }
    }
}

extern "C" void kernel_launch(void* const* d_in, const int* in_sizes, int n_in,
                              void* d_out, int out_size)
{
    const float* q   = (const float*)d_in[0];
    const float* k   = (const float*)d_in[1];
    const float* v   = (const float*)d_in[2];
    const int*   idx = (const int*)d_in[3];
    float* out = (float*)d_out;

    int smem = (W2*CC + KC*KPAD + KC*CC + W2*SPAD) * (int)sizeof(float); // 98784 B
    cudaFuncSetAttribute(wsa_kernel, cudaFuncAttributeMaxDynamicSharedMemorySize, smem);

    dim3 grid(NW, HEADS, 4);
    wsa_kernel<<<grid, 256, smem>>>(q, k, v, idx, out);
}

// round 2
// speedup vs baseline: 1.4553x; 1.4553x over previous
#include <cuda_runtime.h>
#include <math.h>

#define HH 112
#define CC 32
#define W2 49
#define TOPK 4
#define KC 196
#define NW 256
#define HEADS 8
#define SCALEF 0.17677669529663687f   // 32^-0.5

#define QROWS 64     // Q padded rows for M tiles
#define KROWS 200    // K/V padded rows (K-dim of PV / N-dim of QK)
#define KPAD 36      // row stride for Qs/Ks/Vs (≡4 mod 32 -> conflict-free frags)
#define SPAD 204     // row stride for S (≡12 mod 32 -> conflict-free frags)
#define SROWS 49

__device__ __forceinline__ unsigned f2tf(float x) {
    unsigned r; asm("cvt.rna.tf32.f32 %0, %1;" : "=r"(r) : "f"(x)); return r;
}
__device__ __forceinline__ void mma_tf32(float& c0, float& c1, float& c2, float& c3,
                                         unsigned a0, unsigned a1, unsigned a2, unsigned a3,
                                         unsigned b0, unsigned b1) {
    asm volatile("mma.sync.aligned.m16n8k8.row.col.f32.tf32.tf32.f32 "
                 "{%0,%1,%2,%3}, {%4,%5,%6,%7}, {%8,%9}, {%0,%1,%2,%3};"
                 : "+f"(c0), "+f"(c1), "+f"(c2), "+f"(c3)
                 : "r"(a0), "r"(a1), "r"(a2), "r"(a3), "r"(b0), "r"(b1));
}

__global__ __launch_bounds__(256)
void wsa_kernel(const float* __restrict__ q, const float* __restrict__ k,
                const float* __restrict__ v, const int* __restrict__ indices,
                float* __restrict__ out)
{
    extern __shared__ float sm[];
    float* Qs = sm;                     // 64*36  = 2304
    float* Ks = Qs + QROWS*KPAD;        // 200*36 = 7200
    float* Vs = Ks + KROWS*KPAD;        // 200*36 = 7200
    float* S  = Vs + KROWS*KPAD;        // 49*204 = 9996   (total 106800 B)

    __shared__ int sIdx[TOPK];

    const int w = blockIdx.x;
    const int h = blockIdx.y;
    const int b = blockIdx.z;
    const int t = threadIdx.x;
    const int wy = w >> 4, wx = w & 15;

    const size_t base = ((size_t)(b*HEADS + h)) * (size_t)(HH*HH*CC);
    const float* qb = q + base;
    const float* kb = k + base;
    const float* vb = v + base;

    if (t < TOPK)
        sIdx[t] = indices[(((size_t)(b*HEADS + h))*NW + w)*TOPK + t];

    // ---- zero the pad regions (Q rows 49..63, K/V rows 196..199, cols 0..31) ----
    for (int i = t; i < 736; i += 256) {
        if (i < 480)      { int r = 49  + i/32;        Qs[r*KPAD + (i & 31)] = 0.f; }
        else if (i < 608) { int j = i - 480;           Ks[(196 + j/32)*KPAD + (j & 31)] = 0.f; }
        else              { int j = i - 608;           Vs[(196 + j/32)*KPAD + (j & 31)] = 0.f; }
    }

    // ---- load Q window (scale folded in) ----
    for (int i = t; i < W2*8; i += 256) {
        int p = i >> 3, c4 = (i & 7) << 2;
        int y = wy*7 + p/7, x = wx*7 + p%7;
        float4 qq = *(const float4*)(qb + ((size_t)(y*HH + x))*CC + c4);
        qq.x *= SCALEF; qq.y *= SCALEF; qq.z *= SCALEF; qq.w *= SCALEF;
        *(float4*)(Qs + p*KPAD + c4) = qq;
    }
    __syncthreads();

    // ---- gather K,V: topk windows x 49 rows x 32 ch ----
    for (int i = t; i < KC*8; i += 256) {
        int row = i >> 3, c4 = (i & 7) << 2;
        int tt = row / W2, p = row % W2;
        int ws = sIdx[tt];
        int y = (ws >> 4)*7 + p/7, x = (ws & 15)*7 + p%7;
        size_t off = ((size_t)(y*HH + x))*CC + c4;
        *(float4*)(Ks + row*KPAD + c4) = *(const float4*)(kb + off);
        *(float4*)(Vs + row*KPAD + c4) = *(const float4*)(vb + off);
    }
    __syncthreads();

    const int lane = t & 31, warp = t >> 5;
    const int g = lane >> 2, c = lane & 3;
    const int mt = warp & 3, nh = warp >> 2;
    const int r0 = mt*16 + g, r1 = r0 + 8;

    // ---- phase 2: S = (Q*scale) @ K^T via tf32 mma ----
    {
        unsigned A[16];
        #pragma unroll
        for (int kt = 0; kt < 4; kt++) {
            A[kt*4+0] = f2tf(Qs[r0*KPAD + kt*8 + c]);
            A[kt*4+1] = f2tf(Qs[r1*KPAD + kt*8 + c]);
            A[kt*4+2] = f2tf(Qs[r0*KPAD + kt*8 + c + 4]);
            A[kt*4+3] = f2tf(Qs[r1*KPAD + kt*8 + c + 4]);
        }
        int nt0 = nh ? 13 : 0, nt1 = nh ? 25 : 13;
        for (int nt = nt0; nt < nt1; nt++) {
            float c0 = 0.f, c1 = 0.f, c2 = 0.f, c3 = 0.f;
            int krow = nt*8 + g;
            #pragma unroll
            for (int kt = 0; kt < 4; kt++) {
                unsigned b0 = f2tf(Ks[krow*KPAD + kt*8 + c]);
                unsigned b1 = f2tf(Ks[krow*KPAD + kt*8 + c + 4]);
                mma_tf32(c0, c1, c2, c3, A[kt*4], A[kt*4+1], A[kt*4+2], A[kt*4+3], b0, b1);
            }
            int col = nt*8 + c*2;
            if (r0 < SROWS) { S[r0*SPAD + col] = c0; S[r0*SPAD + col + 1] = c1; }
            if (r1 < SROWS) { S[r1*SPAD + col] = c2; S[r1*SPAD + col + 1] = c3; }
        }
    }
    __syncthreads();

    // ---- phase 3: row softmax (one warp per row, rows strided by 8) ----
    for (int p = warp; p < W2; p += 8) {
        float vals[7];
        float m = -INFINITY;
        #pragma unroll
        for (int it = 0; it < 7; it++) {
            int j = lane + (it << 5);
            float x = (j < KC) ? S[p*SPAD + j] : -INFINITY;
            vals[it] = x;
            m = fmaxf(m, x);
        }
        #pragma unroll
        for (int o = 16; o > 0; o >>= 1)
            m = fmaxf(m, __shfl_xor_sync(0xffffffffu, m, o));
        float s = 0.f;
        #pragma unroll
        for (int it = 0; it < 7; it++) {
            float e = __expf(vals[it] - m);
            vals[it] = e; s += e;
        }
        #pragma unroll
        for (int o = 16; o > 0; o >>= 1)
            s += __shfl_xor_sync(0xffffffffu, s, o);
        float inv = 1.0f / s;
        #pragma unroll
        for (int it = 0; it < 7; it++) {
            int j = lane + (it << 5);
            if (j < KC) S[p*SPAD + j] = vals[it] * inv;
        }
    }
    __syncthreads();

    // ---- phase 4: O = P @ V via tf32 mma; warp owns (mt, 2 n-tiles) ----
    {
        float acc[2][4] = {};
        #pragma unroll 1
        for (int kt = 0; kt < 25; kt++) {
            unsigned a0 = (r0 < SROWS) ? f2tf(S[r0*SPAD + kt*8 + c])     : 0u;
            unsigned a1 = (r1 < SROWS) ? f2tf(S[r1*SPAD + kt*8 + c])     : 0u;
            unsigned a2 = (r0 < SROWS) ? f2tf(S[r0*SPAD + kt*8 + c + 4]) : 0u;
            unsigned a3 = (r1 < SROWS) ? f2tf(S[r1*SPAD + kt*8 + c + 4]) : 0u;
            #pragma unroll
            for (int q2 = 0; q2 < 2; q2++) {
                int nt = nh*2 + q2;
                unsigned b0 = f2tf(Vs[(kt*8 + c)*KPAD     + nt*8 + g]);
                unsigned b1 = f2tf(Vs[(kt*8 + c + 4)*KPAD + nt*8 + g]);
                mma_tf32(acc[q2][0], acc[q2][1], acc[q2][2], acc[q2][3],
                         a0, a1, a2, a3, b0, b1);
            }
        }
        // ---- epilogue: out[b, y, x, h*32 + col] ----
        float* ob = out + ((size_t)b*(HH*HH))*256 + h*CC;
        #pragma unroll
        for (int q2 = 0; q2 < 2; q2++) {
            int nt = nh*2 + q2;
            int col = nt*8 + c*2;
            if (r0 < SROWS) {
                int y = wy*7 + r0/7, x = wx*7 + r0%7;
                *(float2*)(ob + (size_t)(y*HH + x)*256 + col) = make_float2(acc[q2][0], acc[q2][1]);
            }
            if (r1 < SROWS) {
                int y = wy*7 + r1/7, x = wx*7 + r1%7;
                *(float2*)(ob + (size_t)(y*HH + x)*256 + col) = make_float2(acc[q2][2], acc[q2][3]);
            }
        }
    }
}

extern "C" void kernel_launch(void* const* d_in, const int* in_sizes, int n_in,
                              void* d_out, int out_size)
{
    const float* q   = (const float*)d_in[0];
    const float* k   = (const float*)d_in[1];
    const float* v   = (const float*)d_in[2];
    const int*   idx = (const int*)d_in[3];
    float* out = (float*)d_out;

    int smem = (QROWS*KPAD + 2*KROWS*KPAD + SROWS*SPAD) * (int)sizeof(float); // 106800 B
    cudaFuncSetAttribute(wsa_kernel, cudaFuncAttributeMaxDynamicSharedMemorySize, smem);

    dim3 grid(NW, HEADS, 4);
    wsa_kernel<<<grid, 256, smem>>>(q, k, v, idx, out);
}

// round 3
// speedup vs baseline: 1.6209x; 1.1138x over previous
#include <cuda_runtime.h>
#include <math.h>

#define HH 112
#define CC 32
#define W2 49
#define TOPK 4
#define KC 196
#define NW 256
#define HEADS 8
#define SCALEF 0.17677669529663687f   // 32^-0.5

// fragment-permuted smem layouts
#define QS 36      // Qp row stride (floats)
#define KS 36      // Kp row stride
#define VTS 228    // Vt per-channel stride
#define VS1 56     // Vt per-(row&3) substride
#define SS 228     // Sp row stride
#define SC 56      // Sp per-(col&3) substride

#define QP_OFF 0        // 64 rows * 36
#define KP_OFF 2304     // 200 rows * 36
#define VT_OFF 9504     // 32 ch * 228
#define SP_OFF 16800    // 49 rows * 228
#define SM_TOT 27972    // floats  -> 111888 bytes

__device__ __forceinline__ unsigned f2tf(float x) {
    unsigned r; asm("cvt.rna.tf32.f32 %0, %1;" : "=r"(r) : "f"(x)); return r;
}
__device__ __forceinline__ float tfbits(float x) {
    unsigned r = f2tf(x); return __uint_as_float(r);
}
__device__ __forceinline__ void mma_tf32(float* cc,
                                         unsigned a0, unsigned a1, unsigned a2, unsigned a3,
                                         unsigned b0, unsigned b1) {
    asm volatile("mma.sync.aligned.m16n8k8.row.col.f32.tf32.tf32.f32 "
                 "{%0,%1,%2,%3}, {%4,%5,%6,%7}, {%8,%9}, {%0,%1,%2,%3};"
                 : "+f"(cc[0]), "+f"(cc[1]), "+f"(cc[2]), "+f"(cc[3])
                 : "r"(a0), "r"(a1), "r"(a2), "r"(a3), "r"(b0), "r"(b1));
}

__global__ __launch_bounds__(256, 2)
void wsa_kernel(const float* __restrict__ q, const float* __restrict__ k,
                const float* __restrict__ v, const int* __restrict__ indices,
                float* __restrict__ out)
{
    extern __shared__ float sm[];
    float* Qp = sm + QP_OFF;
    float* Kp = sm + KP_OFF;
    float* Vt = sm + VT_OFF;
    float* Sp = sm + SP_OFF;
    float* pm = sm;          // reduction scratch (overlaps Qp rows 0-7, dead by then)
    float* ps = sm + 128;

    __shared__ int sIdx[TOPK];

    const int w = blockIdx.x;
    const int h = blockIdx.y;
    const int b = blockIdx.z;
    const int t = threadIdx.x;
    const int wy = w >> 4, wx = w & 15;

    const size_t base = ((size_t)(b*HEADS + h)) * (size_t)(HH*HH*CC);
    const float* qb = q + base;
    const float* kb = k + base;
    const float* vb = v + base;

    if (t < TOPK)
        sIdx[t] = indices[(((size_t)(b*HEADS + h))*NW + w)*TOPK + t];

    // ---- zero pads: Qp rows 49-63 (540), Kp rows 196-199 (144), Vt m=49 (128) ----
    for (int i = t; i < 812; i += 256) {
        if (i < 540)        Qp[49*QS + i] = 0.f;
        else if (i < 684)   Kp[196*KS + (i - 540)] = 0.f;
        else {
            int j = i - 684;                 // j = ch*4 + cblk
            Vt[(j >> 2)*VTS + (j & 3)*VS1 + 49] = 0.f;
        }
    }

    // ---- Q load: permuted + scaled + tf32 ----
    for (int i = t; i < W2*8; i += 256) {
        int p = i >> 3, c4g = i & 7;
        int y = wy*7 + p/7, x = wx*7 + p%7;
        float4 qq = *(const float4*)(qb + ((size_t)(y*HH + x))*CC + (c4g << 2));
        float* qd = Qp + p*QS + c4g;
        qd[0]  = tfbits(qq.x * SCALEF);
        qd[8]  = tfbits(qq.y * SCALEF);
        qd[16] = tfbits(qq.z * SCALEF);
        qd[24] = tfbits(qq.w * SCALEF);
    }
    __syncthreads();   // sIdx visible

    // ---- gather K,V: row-in-lane-low layout for conflict-free permuted stores ----
    for (int i = t; i < 1600; i += 256) {
        int row = ((i >> 6) << 3) + (i & 7);
        if (row < KC) {
            int c4g = (i >> 3) & 7;
            int tt = row / W2, p = row - tt*W2;
            int ws = sIdx[tt];
            int y = (ws >> 4)*7 + p/7, x = (ws & 15)*7 + p%7;
            size_t off = ((size_t)(y*HH + x))*CC + (c4g << 2);
            float4 kk = *(const float4*)(kb + off);
            float4 vv = *(const float4*)(vb + off);
            float* kd = Kp + row*KS + c4g;
            kd[0]  = tfbits(kk.x);
            kd[8]  = tfbits(kk.y);
            kd[16] = tfbits(kk.z);
            kd[24] = tfbits(kk.w);
            float* vd = Vt + (c4g << 2)*VTS + (row & 3)*VS1 + (row >> 2);
            vd[0]     = tfbits(vv.x);
            vd[VTS]   = tfbits(vv.y);
            vd[2*VTS] = tfbits(vv.z);
            vd[3*VTS] = tfbits(vv.w);
        }
    }
    __syncthreads();

    const int lane = t & 31, warp = t >> 5;
    const int g = lane >> 2, c = lane & 3;
    const int mt = warp & 3, nh = warp >> 2;
    const int r0 = mt*16 + g, r1 = r0 + 8;
    const bool w0 = (r0 < W2), w1 = (r1 < W2);

    // ---- phase 2: S = Q@K^T, accumulators stay in registers ----
    float acc[13][4];
    {
        uint4 qa0 = *(const uint4*)(Qp + r0*QS + c*8);
        uint4 qa1 = *(const uint4*)(Qp + r0*QS + c*8 + 4);
        uint4 qb0 = *(const uint4*)(Qp + r1*QS + c*8);
        uint4 qb1 = *(const uint4*)(Qp + r1*QS + c*8 + 4);
        #pragma unroll
        for (int ntl = 0; ntl < 13; ntl++) {
            acc[ntl][0] = acc[ntl][1] = acc[ntl][2] = acc[ntl][3] = 0.f;
            int krow = (nh*13 + ntl)*8 + g;
            uint4 kb0 = *(const uint4*)(Kp + krow*KS + c*8);
            uint4 kb1 = *(const uint4*)(Kp + krow*KS + c*8 + 4);
            mma_tf32(acc[ntl], qa0.x, qb0.x, qa0.y, qb0.y, kb0.x, kb0.y);
            mma_tf32(acc[ntl], qa0.z, qb0.z, qa0.w, qb0.w, kb0.z, kb0.w);
            mma_tf32(acc[ntl], qa1.x, qb1.x, qa1.y, qb1.y, kb1.x, kb1.y);
            mma_tf32(acc[ntl], qa1.z, qb1.z, qa1.w, qb1.w, kb1.z, kb1.w);
        }
    }
    // mask pad columns (cols 196-199 at ntg=24, whole ntg=25)
    if (nh) {
        if (c >= 2) { acc[11][0] = acc[11][1] = acc[11][2] = acc[11][3] = -INFINITY; }
        acc[12][0] = acc[12][1] = acc[12][2] = acc[12][3] = -INFINITY;
    }
    __syncthreads();   // all warps done reading Qp; pm/ps scratch now safe

    // ---- softmax on register accumulators ----
    {
        float m0 = -INFINITY, m1 = -INFINITY;
        #pragma unroll
        for (int ntl = 0; ntl < 13; ntl++) {
            m0 = fmaxf(m0, fmaxf(acc[ntl][0], acc[ntl][1]));
            m1 = fmaxf(m1, fmaxf(acc[ntl][2], acc[ntl][3]));
        }
        m0 = fmaxf(m0, __shfl_xor_sync(0xffffffffu, m0, 1));
        m0 = fmaxf(m0, __shfl_xor_sync(0xffffffffu, m0, 2));
        m1 = fmaxf(m1, __shfl_xor_sync(0xffffffffu, m1, 1));
        m1 = fmaxf(m1, __shfl_xor_sync(0xffffffffu, m1, 2));
        if (c == 0) { pm[nh*64 + r0] = m0; pm[nh*64 + r1] = m1; }
        __syncthreads();
        float M0 = fmaxf(pm[r0], pm[64 + r0]);
        float M1 = fmaxf(pm[r1], pm[64 + r1]);

        float s0 = 0.f, s1 = 0.f;
        #pragma unroll
        for (int ntl = 0; ntl < 13; ntl++) {
            acc[ntl][0] = __expf(acc[ntl][0] - M0);
            acc[ntl][1] = __expf(acc[ntl][1] - M0);
            acc[ntl][2] = __expf(acc[ntl][2] - M1);
            acc[ntl][3] = __expf(acc[ntl][3] - M1);
            s0 += acc[ntl][0] + acc[ntl][1];
            s1 += acc[ntl][2] + acc[ntl][3];
        }
        s0 += __shfl_xor_sync(0xffffffffu, s0, 1);
        s0 += __shfl_xor_sync(0xffffffffu, s0, 2);
        s1 += __shfl_xor_sync(0xffffffffu, s1, 1);
        s1 += __shfl_xor_sync(0xffffffffu, s1, 2);
        if (c == 0) { ps[nh*64 + r0] = s0; ps[nh*64 + r1] = s1; }
        __syncthreads();
        float i0 = 1.0f / (ps[r0] + ps[64 + r0]);
        float i1 = 1.0f / (ps[r1] + ps[64 + r1]);

        // store P (tf32) into permuted Sp
        float* sp0 = Sp + r0*SS;
        float* sp1 = Sp + r1*SS;
        int cA = ((2*c) & 3) * SC;
        int cB = ((2*c + 1) & 3) * SC;
        int mo = (c >> 1);
        #pragma unroll
        for (int ntl = 0; ntl < 13; ntl++) {
            int mm = 2*(nh*13 + ntl) + mo;
            if (w0) {
                sp0[cA + mm] = tfbits(acc[ntl][0] * i0);
                sp0[cB + mm] = tfbits(acc[ntl][1] * i0);
            }
            if (w1) {
                sp1[cA + mm] = tfbits(acc[ntl][2] * i1);
                sp1[cB + mm] = tfbits(acc[ntl][3] * i1);
            }
        }
    }
    __syncthreads();

    // ---- phase 4: O = P @ V, even/odd kt split for shorter HMMA chains ----
    {
        float oA[2][4] = {}, oB[2][4] = {};
        const int ch0 = (nh*2)*8 + g, ch1 = ch0 + 8;
        const uint4 z4 = {0u,0u,0u,0u};
        #pragma unroll
        for (int ktp = 0; ktp < 12; ktp++) {
            uint4 a0v = z4, a1v = z4;
            if (w0) a0v = *(const uint4*)(Sp + r0*SS + c*SC + 4*ktp);
            if (w1) a1v = *(const uint4*)(Sp + r1*SS + c*SC + 4*ktp);
            uint4 b0v = *(const uint4*)(Vt + ch0*VTS + c*VS1 + 4*ktp);
            uint4 b1v = *(const uint4*)(Vt + ch1*VTS + c*VS1 + 4*ktp);
            mma_tf32(oA[0], a0v.x, a1v.x, a0v.y, a1v.y, b0v.x, b0v.y);
            mma_tf32(oA[1], a0v.x, a1v.x, a0v.y, a1v.y, b1v.x, b1v.y);
            mma_tf32(oB[0], a0v.z, a1v.z, a0v.w, a1v.w, b0v.z, b0v.w);
            mma_tf32(oB[1], a0v.z, a1v.z, a0v.w, a1v.w, b1v.z, b1v.w);
        }
        {   // tail kt = 24 (m = 48, 49)
            uint2 a0t = {0u,0u}, a1t = {0u,0u};
            if (w0) a0t = *(const uint2*)(Sp + r0*SS + c*SC + 48);
            if (w1) a1t = *(const uint2*)(Sp + r1*SS + c*SC + 48);
            uint2 b0t = *(const uint2*)(Vt + ch0*VTS + c*VS1 + 48);
            uint2 b1t = *(const uint2*)(Vt + ch1*VTS + c*VS1 + 48);
            mma_tf32(oA[0], a0t.x, a1t.x, a0t.y, a1t.y, b0t.x, b0t.y);
            mma_tf32(oA[1], a0t.x, a1t.x, a0t.y, a1t.y, b1t.x, b1t.y);
        }

        float* ob = out + ((size_t)b*(HH*HH))*256 + h*CC;
        #pragma unroll
        for (int q2 = 0; q2 < 2; q2++) {
            int colb = (nh*2 + q2)*8 + c*2;
            float v0 = oA[q2][0] + oB[q2][0];
            float v1 = oA[q2][1] + oB[q2][1];
            float v2 = oA[q2][2] + oB[q2][2];
            float v3 = oA[q2][3] + oB[q2][3];
            if (w0) {
                int y = wy*7 + r0/7, x = wx*7 + r0%7;
                *(float2*)(ob + (size_t)(y*HH + x)*256 + colb) = make_float2(v0, v1);
            }
            if (w1) {
                int y = wy*7 + r1/7, x = wx*7 + r1%7;
                *(float2*)(ob + (size_t)(y*HH + x)*256 + colb) = make_float2(v2, v3);
            }
        }
    }
}

extern "C" void kernel_launch(void* const* d_in, const int* in_sizes, int n_in,
                              void* d_out, int out_size)
{
    const float* q   = (const float*)d_in[0];
    const float* k   = (const float*)d_in[1];
    const float* v   = (const float*)d_in[2];
    const int*   idx = (const int*)d_in[3];
    float* out = (float*)d_out;

    int smem = SM_TOT * (int)sizeof(float);   // 111888 B
    cudaFuncSetAttribute(wsa_kernel, cudaFuncAttributeMaxDynamicSharedMemorySize, smem);

    dim3 grid(NW, HEADS, 4);
    wsa_kernel<<<grid, 256, smem>>>(q, k, v, idx, out);
}